// round 14
// baseline (speedup 1.0000x reference)
#include <cuda_runtime.h>
#include <cuda_bf16.h>
#include <cuda_fp16.h>
#include <cstdint>

#define NX_MAX 100000
#define NC_MAX 50000
#define NR_MAX 1000
#define HID 64
#define EMAX 4200000

__device__ float g_agg[(size_t)NX_MAX * HID];
__device__ float g_txx[(size_t)NX_MAX * HID / 2];
__device__ float g_tcx[(size_t)NC_MAX * HID / 2];
__device__ float g_trx[(size_t)NR_MAX * HID / 2];
__device__ int   g_off[NX_MAX + 1];
__device__ int   g_cur[NX_MAX];          // zero at load; re-zeroed each call (in-shadow)
__device__ int   g_bsum[256];
__device__ unsigned int g_eidx[EMAX];

// ---------- helpers ----------
__device__ __forceinline__ uint32_t smem_to_u32(const void* p) {
    uint32_t a;
    asm("{ .reg .u64 t; cvta.to.shared.u64 t, %1; cvt.u32.u64 %0, t; }"
        : "=r"(a) : "l"(p));
    return a;
}

__device__ __forceinline__ void split4(const float4 v, unsigned long long& hi,
                                       unsigned long long& lo) {
    __nv_bfloat16 h0 = __float2bfloat16_rn(v.x);
    __nv_bfloat16 h1 = __float2bfloat16_rn(v.y);
    __nv_bfloat16 h2 = __float2bfloat16_rn(v.z);
    __nv_bfloat16 h3 = __float2bfloat16_rn(v.w);
    __nv_bfloat16 l0 = __float2bfloat16_rn(v.x - __bfloat162float(h0));
    __nv_bfloat16 l1 = __float2bfloat16_rn(v.y - __bfloat162float(h1));
    __nv_bfloat16 l2 = __float2bfloat16_rn(v.z - __bfloat162float(h2));
    __nv_bfloat16 l3 = __float2bfloat16_rn(v.w - __bfloat162float(h3));
    __nv_bfloat162 ha = __halves2bfloat162(h0, h1), hb = __halves2bfloat162(h2, h3);
    __nv_bfloat162 la = __halves2bfloat162(l0, l1), lb = __halves2bfloat162(l2, l3);
    hi = (unsigned long long)*reinterpret_cast<uint32_t*>(&ha) |
         ((unsigned long long)*reinterpret_cast<uint32_t*>(&hb) << 32);
    lo = (unsigned long long)*reinterpret_cast<uint32_t*>(&la) |
         ((unsigned long long)*reinterpret_cast<uint32_t*>(&lb) << 32);
}

__device__ __forceinline__ void ldsm_x4(uint32_t* r, uint32_t addr) {
    asm volatile("ldmatrix.sync.aligned.m8n8.x4.shared.b16 {%0,%1,%2,%3}, [%4];"
                 : "=r"(r[0]), "=r"(r[1]), "=r"(r[2]), "=r"(r[3]) : "r"(addr));
}
__device__ __forceinline__ void mma16816(float* c, const uint32_t* a,
                                         uint32_t b0, uint32_t b1) {
    asm volatile(
        "mma.sync.aligned.m16n8k16.row.col.f32.bf16.bf16.f32 "
        "{%0,%1,%2,%3}, {%4,%5,%6,%7}, {%8,%9}, {%0,%1,%2,%3};"
        : "+f"(c[0]), "+f"(c[1]), "+f"(c[2]), "+f"(c[3])
        : "r"(a[0]), "r"(a[1]), "r"(a[2]), "r"(a[3]), "r"(b0), "r"(b1));
}

// ---------------------------------------------------------------------------
// hmma_gemm_dual: stage A once, two weight sets, two outputs.
// ---------------------------------------------------------------------------
#define D_AH   0
#define D_AL   16384
#define D_W1H  32768
#define D_W1L  40960
#define D_W2H  49152
#define D_W2L  57344
#define D_BI1  65536
#define D_BI2  65792
#define SMEM_DU 66048

template <int F>
__global__ void __launch_bounds__(256, 2) hmma_gemm_dual(
    const float* __restrict__ X, int N,
    const float* __restrict__ W1, const float* __restrict__ B1,
    float* __restrict__ Y1,
    const float* __restrict__ W2, const float* __restrict__ B2,
    __half* __restrict__ Y2)
{
    constexpr int NG = F / 4;
    constexpr int KS = F / 16;

    extern __shared__ char smem[];
    const uint32_t sb = smem_to_u32(smem);
    const int tid  = threadIdx.x;
    const int wid  = tid >> 5;
    const int lane = tid & 31;
    const int rowBase = blockIdx.x * 128;

    if (tid < 64) {
        *reinterpret_cast<float*>(smem + D_BI1 + tid * 4) = B1[tid];
        *reinterpret_cast<float*>(smem + D_BI2 + tid * 4) = B2[tid];
    }

    {
        const float4* X4 = reinterpret_cast<const float4*>(X);
        for (int i = tid; i < 128 * NG; i += 256) {
            int r = i / NG;
            int g = i - r * NG;
            int row = rowBase + r;
            float4 v = make_float4(0.f, 0.f, 0.f, 0.f);
            if (row < N) v = X4[(size_t)row * NG + g];
            unsigned long long hi, lo;
            split4(v, hi, lo);
            uint32_t off = r * 128 + ((g * 8) ^ ((r & 7) << 4));
            *reinterpret_cast<unsigned long long*>(smem + D_AH + off) = hi;
            *reinterpret_cast<unsigned long long*>(smem + D_AL + off) = lo;
        }
    }
    {
        const float4* W14 = reinterpret_cast<const float4*>(W1);
        const float4* W24 = reinterpret_cast<const float4*>(W2);
        for (int i = tid; i < 64 * NG; i += 256) {
            int n = i / NG;
            int g = i - n * NG;
            uint32_t off = n * 128 + ((g * 8) ^ ((n & 7) << 4));
            {
                float4 v = W14[(size_t)n * NG + g];
                unsigned long long hi, lo;
                split4(v, hi, lo);
                *reinterpret_cast<unsigned long long*>(smem + D_W1H + off) = hi;
                *reinterpret_cast<unsigned long long*>(smem + D_W1L + off) = lo;
            }
            {
                float4 v = W24[(size_t)n * NG + g];
                unsigned long long hi, lo;
                split4(v, hi, lo);
                *reinterpret_cast<unsigned long long*>(smem + D_W2H + off) = hi;
                *reinterpret_cast<unsigned long long*>(smem + D_W2L + off) = lo;
            }
        }
    }
    __syncthreads();

    const int rA   = wid * 16 + (lane & 7) + ((lane >> 3) & 1) * 8;
    const uint32_t aOff  = ((lane >> 4) & 1) * 16;
    const uint32_t aXor  = (rA & 7) << 4;
    const uint32_t aBaseH = sb + D_AH + rA * 128;
    const uint32_t aBaseL = sb + D_AL + rA * 128;

    uint32_t bRow[4], bXor[4];
    const uint32_t bOff = ((lane >> 3) & 1) * 16;
#pragma unroll
    for (int p = 0; p < 4; p++) {
        int n = p * 16 + ((lane >> 4) & 1) * 8 + (lane & 7);
        bXor[p] = (n & 7) << 4;
        bRow[p] = n * 128;
    }

    float c1[8][4], c2[8][4];
#pragma unroll
    for (int nt = 0; nt < 8; nt++)
#pragma unroll
        for (int q = 0; q < 4; q++) { c1[nt][q] = 0.f; c2[nt][q] = 0.f; }

#pragma unroll
    for (int ks = 0; ks < KS; ks++) {
        uint32_t ah[4], al[4];
        ldsm_x4(ah, aBaseH + ((ks * 32 + aOff) ^ aXor));
        ldsm_x4(al, aBaseL + ((ks * 32 + aOff) ^ aXor));
#pragma unroll
        for (int p = 0; p < 4; p++) {
            const uint32_t ko = (ks * 32 + bOff) ^ bXor[p];
            {
                uint32_t bh[4], bl[4];
                ldsm_x4(bh, sb + D_W1H + bRow[p] + ko);
                ldsm_x4(bl, sb + D_W1L + bRow[p] + ko);
                mma16816(c1[2 * p],     ah, bh[0], bh[1]);
                mma16816(c1[2 * p],     ah, bl[0], bl[1]);
                mma16816(c1[2 * p],     al, bh[0], bh[1]);
                mma16816(c1[2 * p + 1], ah, bh[2], bh[3]);
                mma16816(c1[2 * p + 1], ah, bl[2], bl[3]);
                mma16816(c1[2 * p + 1], al, bh[2], bh[3]);
            }
            {
                uint32_t bh[4], bl[4];
                ldsm_x4(bh, sb + D_W2H + bRow[p] + ko);
                ldsm_x4(bl, sb + D_W2L + bRow[p] + ko);
                mma16816(c2[2 * p],     ah, bh[0], bh[1]);
                mma16816(c2[2 * p],     ah, bl[0], bl[1]);
                mma16816(c2[2 * p],     al, bh[0], bh[1]);
                mma16816(c2[2 * p + 1], ah, bh[2], bh[3]);
                mma16816(c2[2 * p + 1], ah, bl[2], bl[3]);
                mma16816(c2[2 * p + 1], al, bh[2], bh[3]);
            }
        }
    }

    const int g = lane >> 2;
    const int t = lane & 3;
    const int row0 = rowBase + wid * 16 + g;
    const float* Bs1 = reinterpret_cast<const float*>(smem + D_BI1);
    const float* Bs2 = reinterpret_cast<const float*>(smem + D_BI2);
#pragma unroll
    for (int nt = 0; nt < 8; nt++) {
        int col = nt * 8 + 2 * t;
        {
            float bx = Bs1[col], by = Bs1[col + 1];
            float v0 = fmaxf(c1[nt][0] + bx, 0.f), v1 = fmaxf(c1[nt][1] + by, 0.f);
            float v2 = fmaxf(c1[nt][2] + bx, 0.f), v3 = fmaxf(c1[nt][3] + by, 0.f);
            if (row0 < N)
                *reinterpret_cast<float2*>(Y1 + (size_t)row0 * 64 + col) =
                    make_float2(v0, v1);
            if (row0 + 8 < N)
                *reinterpret_cast<float2*>(Y1 + (size_t)(row0 + 8) * 64 + col) =
                    make_float2(v2, v3);
        }
        {
            float bx = Bs2[col], by = Bs2[col + 1];
            float v0 = fmaxf(c2[nt][0] + bx, 0.f), v1 = fmaxf(c2[nt][1] + by, 0.f);
            float v2 = fmaxf(c2[nt][2] + bx, 0.f), v3 = fmaxf(c2[nt][3] + by, 0.f);
            if (row0 < N)
                *reinterpret_cast<__half2*>(Y2 + (size_t)row0 * 64 + col) =
                    __floats2half2_rn(v0, v1);
            if (row0 + 8 < N)
                *reinterpret_cast<__half2*>(Y2 + (size_t)(row0 + 8) * 64 + col) =
                    __floats2half2_rn(v2, v3);
        }
    }
}

// ---------------- small GEMM for r (F=48, N=1000) ----------------
template <int F, bool RELU, typename OUT>
__global__ void __launch_bounds__(128) gemm_small(
    const float* __restrict__ X, int N,
    const float* __restrict__ W, const float* __restrict__ B,
    OUT* __restrict__ Y)
{
    __shared__ float Wt[F * 64];
    __shared__ float Bs[64];
    const int tid = threadIdx.x;
    for (int i = tid; i < F * 64; i += 128) {
        int j = i / F;
        int k = i - j * F;
        Wt[k * 64 + j] = W[i];
    }
    if (tid < 64) Bs[tid] = B[tid];
    __syncthreads();
    const int row = blockIdx.x * 128 + tid;
    if (row >= N) return;
    float4 acc[16];
    const float4* Bs4 = reinterpret_cast<const float4*>(Bs);
#pragma unroll
    for (int j = 0; j < 16; j++) acc[j] = Bs4[j];
    const float4* X4  = reinterpret_cast<const float4*>(X + (size_t)row * F);
    const float4* Wt4 = reinterpret_cast<const float4*>(Wt);
#pragma unroll 2
    for (int k4 = 0; k4 < F / 4; k4++) {
        const float4 xv = X4[k4];
#pragma unroll
        for (int kk = 0; kk < 4; kk++) {
            const float xs = (kk == 0) ? xv.x : (kk == 1) ? xv.y : (kk == 2) ? xv.z : xv.w;
            const float4* wrow = Wt4 + (size_t)(k4 * 4 + kk) * 16;
#pragma unroll
            for (int j = 0; j < 16; j++) {
                float4 w = wrow[j];
                acc[j].x += xs * w.x; acc[j].y += xs * w.y;
                acc[j].z += xs * w.z; acc[j].w += xs * w.w;
            }
        }
    }
#pragma unroll
    for (int j = 0; j < 16; j++) {
        float4 v = acc[j];
        if (RELU) {
            v.x = fmaxf(v.x, 0.f); v.y = fmaxf(v.y, 0.f);
            v.z = fmaxf(v.z, 0.f); v.w = fmaxf(v.w, 0.f);
        }
        if constexpr (sizeof(OUT) == 2) {
            __half2* p = reinterpret_cast<__half2*>((__half*)Y + (size_t)row * 64 + j * 4);
            p[0] = __floats2half2_rn(v.x, v.y);
            p[1] = __floats2half2_rn(v.z, v.w);
        } else {
            reinterpret_cast<float4*>((float*)Y + (size_t)row * 64)[j] = v;
        }
    }
}

// ---------------- CSR build ----------------
__global__ void zero_kernel(int* p, int n) {
    int i = blockIdx.x * blockDim.x + threadIdx.x;
    if (i < n) p[i] = 0;
}

__global__ void hist_kernel4(const int* __restrict__ dxx, const int* __restrict__ dcx,
                             const int* __restrict__ drx,
                             int Exx, int Ecx, int Erx, int* __restrict__ deg)
{
    int base = (blockIdx.x * blockDim.x + threadIdx.x) * 4;
    int Etot = Exx + Ecx + Erx;
    int d[4];
    int cnt = 0;
#pragma unroll
    for (int j = 0; j < 4; j++) {
        int i = base + j;
        if (i < Etot) {
            if (i < Exx) d[cnt] = dxx[i];
            else if (i < Exx + Ecx) d[cnt] = dcx[i - Exx];
            else d[cnt] = drx[i - Exx - Ecx];
            cnt++;
        }
    }
#pragma unroll
    for (int j = 0; j < 4; j++)
        if (j < cnt) atomicAdd(&deg[d[j]], 1);
}

__global__ void scan1_kernel(const int* __restrict__ deg, int* __restrict__ off,
                             int* __restrict__ bsum, int n)
{
    __shared__ int s[1024];
    int t = threadIdx.x;
    int i = blockIdx.x * 1024 + t;
    int v = (i < n) ? deg[i] : 0;
    s[t] = v;
    __syncthreads();
#pragma unroll
    for (int o = 1; o < 1024; o <<= 1) {
        int a = (t >= o) ? s[t - o] : 0;
        __syncthreads();
        s[t] += a;
        __syncthreads();
    }
    if (i < n) off[i] = s[t] - v;
    if (t == 1023) bsum[blockIdx.x] = s[1023];
}

__global__ void scan2_kernel(int* __restrict__ bsum, int nb, int* __restrict__ off,
                             int n, int Etot)
{
    __shared__ int s[128];
    int t = threadIdx.x;
    int v = (t < nb) ? bsum[t] : 0;
    s[t] = v;
    __syncthreads();
#pragma unroll
    for (int o = 1; o < 128; o <<= 1) {
        int a = (t >= o) ? s[t - o] : 0;
        __syncthreads();
        s[t] += a;
        __syncthreads();
    }
    if (t < nb) bsum[t] = s[t] - v;
    if (t == 0) off[n] = Etot;
}

__global__ void scan3_kernel(int* __restrict__ off, const int* __restrict__ bsum,
                             int* __restrict__ cur, int n)
{
    int i = blockIdx.x * 1024 + threadIdx.x;
    if (i < n) {
        int o = off[i] + bsum[blockIdx.x];
        off[i] = o;
        cur[i] = o;
    }
}

__global__ void fill_kernel4(const int* __restrict__ sxx, const int* __restrict__ dxx,
                             const int* __restrict__ scx, const int* __restrict__ dcx,
                             const int* __restrict__ srx, const int* __restrict__ drx,
                             int Exx, int Ecx, int Erx,
                             int* __restrict__ cur, unsigned int* __restrict__ eidx)
{
    int base = (blockIdx.x * blockDim.x + threadIdx.x) * 4;
    int Etot = Exx + Ecx + Erx;
    int d[4]; unsigned int rec[4];
    int cnt = 0;
#pragma unroll
    for (int j = 0; j < 4; j++) {
        int i = base + j;
        if (i < Etot) {
            int dd, ss; unsigned int rel;
            if (i < Exx)            { dd = dxx[i];             ss = sxx[i];             rel = 0u; }
            else if (i < Exx + Ecx) { dd = dcx[i - Exx];       ss = scx[i - Exx];       rel = 1u; }
            else                    { dd = drx[i - Exx - Ecx]; ss = srx[i - Exx - Ecx]; rel = 2u; }
            d[cnt] = dd;
            rec[cnt] = (rel << 28) | (unsigned int)ss;
            cnt++;
        }
    }
#pragma unroll
    for (int j = 0; j < 4; j++) {
        if (j < cnt) {
            int p = atomicAdd(&cur[d[j]], 1);
            eidx[p] = rec[j];
        }
    }
}

// ---------------------------------------------------------------------------
// gather_pool: fused gather-accumulate + pool GEMV.
// 8 lanes/edge gather (uint4, MLP=8), quarter-merge via shfl, then each warp
// does the 64x64 pool projection in-place (W_pool^T staged in smem) and
// writes x_out directly. agg (self-loop term) is read-only.
// Persistent-ish: each warp strides over rows.
// ---------------------------------------------------------------------------
__device__ __forceinline__ void acc8h(float4& a0, float4& a1,
                                      const __half* __restrict__ txx,
                                      const __half* __restrict__ tcx,
                                      const __half* __restrict__ trx,
                                      unsigned int rr, int q)
{
    const __half* t = (rr >> 28) == 0 ? txx : ((rr >> 28) == 1 ? tcx : trx);
    uint4 h = *reinterpret_cast<const uint4*>(
        t + (size_t)(rr & 0x0FFFFFFFu) * 64 + q * 8);
    const __half2* hp = reinterpret_cast<const __half2*>(&h);
    float2 f0 = __half22float2(hp[0]);
    float2 f1 = __half22float2(hp[1]);
    float2 f2 = __half22float2(hp[2]);
    float2 f3 = __half22float2(hp[3]);
    a0.x += f0.x; a0.y += f0.y; a0.z += f1.x; a0.w += f1.y;
    a1.x += f2.x; a1.y += f2.y; a1.z += f3.x; a1.w += f3.y;
}

__global__ void __launch_bounds__(256) gather_pool(
    const __half* __restrict__ txx, const __half* __restrict__ tcx,
    const __half* __restrict__ trx,
    const float* __restrict__ agg,   // self-loop term (read-only)
    const int* __restrict__ off, const unsigned int* __restrict__ eidx,
    const float* __restrict__ Wp,    // [64][64] row-major
    const float* __restrict__ bp,    // [64]
    float* __restrict__ x_out, int nx)
{
    __shared__ float Wt[64 * 64];    // Wt[k*64 + j] = Wp[j][k]
    __shared__ float bias[64];
    __shared__ float rowS[8][64];

    const int tid = threadIdx.x;
    for (int i = tid; i < 4096; i += 256) {
        int j = i >> 6;
        int k = i & 63;
        Wt[k * 64 + j] = Wp[i];
    }
    if (tid < 64) bias[tid] = bp[tid];
    __syncthreads();

    const int wid  = tid >> 5;
    const int lane = tid & 31;
    const int quarter = lane >> 3;
    const int q       = lane & 7;
    const float bias0 = bias[2 * lane];
    const float bias1 = bias[2 * lane + 1];
    const int nwarp = gridDim.x * 8;
    float* rs = rowS[wid];

    for (int row = blockIdx.x * 8 + wid; row < nx; row += nwarp) {
        const int s = off[row];
        const int e = off[row + 1];

        float4 a0 = make_float4(0.f, 0.f, 0.f, 0.f);
        float4 a1 = make_float4(0.f, 0.f, 0.f, 0.f);

        int i = s;
        for (; i + 32 <= e; i += 32) {
            unsigned int r0 = eidx[i      + quarter];
            unsigned int r1 = eidx[i + 4  + quarter];
            unsigned int r2 = eidx[i + 8  + quarter];
            unsigned int r3 = eidx[i + 12 + quarter];
            unsigned int r4 = eidx[i + 16 + quarter];
            unsigned int r5 = eidx[i + 20 + quarter];
            unsigned int r6 = eidx[i + 24 + quarter];
            unsigned int r7 = eidx[i + 28 + quarter];
            acc8h(a0, a1, txx, tcx, trx, r0, q);
            acc8h(a0, a1, txx, tcx, trx, r1, q);
            acc8h(a0, a1, txx, tcx, trx, r2, q);
            acc8h(a0, a1, txx, tcx, trx, r3, q);
            acc8h(a0, a1, txx, tcx, trx, r4, q);
            acc8h(a0, a1, txx, tcx, trx, r5, q);
            acc8h(a0, a1, txx, tcx, trx, r6, q);
            acc8h(a0, a1, txx, tcx, trx, r7, q);
        }
        for (; i + 16 <= e; i += 16) {
            unsigned int r0 = eidx[i      + quarter];
            unsigned int r1 = eidx[i + 4  + quarter];
            unsigned int r2 = eidx[i + 8  + quarter];
            unsigned int r3 = eidx[i + 12 + quarter];
            acc8h(a0, a1, txx, tcx, trx, r0, q);
            acc8h(a0, a1, txx, tcx, trx, r1, q);
            acc8h(a0, a1, txx, tcx, trx, r2, q);
            acc8h(a0, a1, txx, tcx, trx, r3, q);
        }
        for (; i + 4 <= e; i += 4) {
            acc8h(a0, a1, txx, tcx, trx, eidx[i + quarter], q);
        }
        if (quarter < e - i) {
            acc8h(a0, a1, txx, tcx, trx, eidx[i + quarter], q);
        }

#pragma unroll
        for (int m = 8; m <= 16; m <<= 1) {
            a0.x += __shfl_xor_sync(0xFFFFFFFFu, a0.x, m);
            a0.y += __shfl_xor_sync(0xFFFFFFFFu, a0.y, m);
            a0.z += __shfl_xor_sync(0xFFFFFFFFu, a0.z, m);
            a0.w += __shfl_xor_sync(0xFFFFFFFFu, a0.w, m);
            a1.x += __shfl_xor_sync(0xFFFFFFFFu, a1.x, m);
            a1.y += __shfl_xor_sync(0xFFFFFFFFu, a1.y, m);
            a1.z += __shfl_xor_sync(0xFFFFFFFFu, a1.z, m);
            a1.w += __shfl_xor_sync(0xFFFFFFFFu, a1.w, m);
        }

        // add self-loop term and publish row (8 lanes cover 64 floats)
        if (quarter == 0) {
            const float4* ap = reinterpret_cast<const float4*>(
                agg + (size_t)row * 64 + q * 8);
            float4 b0 = ap[0], b1 = ap[1];
            a0.x += b0.x; a0.y += b0.y; a0.z += b0.z; a0.w += b0.w;
            a1.x += b1.x; a1.y += b1.y; a1.z += b1.z; a1.w += b1.w;
            float4* rp = reinterpret_cast<float4*>(&rs[q * 8]);
            rp[0] = a0;
            rp[1] = a1;
        }
        __syncwarp();

        // pool GEMV: lane computes outputs 2*lane, 2*lane+1
        float acc0 = bias0, acc1 = bias1;
        const float4* rs4 = reinterpret_cast<const float4*>(rs);
#pragma unroll
        for (int k4 = 0; k4 < 16; k4++) {
            float4 rv = rs4[k4];
            const float2* w0 = reinterpret_cast<const float2*>(&Wt[(4 * k4 + 0) * 64]);
            const float2* w1 = reinterpret_cast<const float2*>(&Wt[(4 * k4 + 1) * 64]);
            const float2* w2 = reinterpret_cast<const float2*>(&Wt[(4 * k4 + 2) * 64]);
            const float2* w3 = reinterpret_cast<const float2*>(&Wt[(4 * k4 + 3) * 64]);
            float2 a = w0[lane]; acc0 += rv.x * a.x; acc1 += rv.x * a.y;
            float2 b = w1[lane]; acc0 += rv.y * b.x; acc1 += rv.y * b.y;
            float2 cc = w2[lane]; acc0 += rv.z * cc.x; acc1 += rv.z * cc.y;
            float2 d = w3[lane]; acc0 += rv.w * d.x; acc1 += rv.w * d.y;
        }
        __syncwarp();   // rowS reads done before next iteration's write

        reinterpret_cast<float2*>(x_out + (size_t)row * 64)[lane] =
            make_float2(acc0, acc1);
    }
}

extern "C" void kernel_launch(void* const* d_in, const int* in_sizes, int n_in,
                              void* d_out, int out_size)
{
    const float* x      = (const float*)d_in[0];
    const float* c      = (const float*)d_in[1];
    const float* r      = (const float*)d_in[2];
    const int*   e_xx_s = (const int*)d_in[3];
    const int*   e_xx_d = (const int*)d_in[4];
    const int*   e_cx_s = (const int*)d_in[5];
    const int*   e_cx_d = (const int*)d_in[6];
    const int*   e_rx_s = (const int*)d_in[7];
    const int*   e_rx_d = (const int*)d_in[8];
    const float* W_x    = (const float*)d_in[9];
    const float* b_x    = (const float*)d_in[10];
    const float* W_c    = (const float*)d_in[11];
    const float* b_c    = (const float*)d_in[12];
    const float* W_r    = (const float*)d_in[13];
    const float* b_r    = (const float*)d_in[14];
    const float* W_xx   = (const float*)d_in[15];
    const float* b_xx   = (const float*)d_in[16];
    const float* W_cx   = (const float*)d_in[17];
    const float* b_cx   = (const float*)d_in[18];
    const float* W_rx   = (const float*)d_in[19];
    const float* b_rx   = (const float*)d_in[20];
    const float* W_pool = (const float*)d_in[21];
    const float* b_pool = (const float*)d_in[22];

    const int nx  = in_sizes[0] / 64;
    const int nc  = in_sizes[1] / 32;
    const int nr  = in_sizes[2] / 48;
    const int Exx = in_sizes[3];
    const int Ecx = in_sizes[5];
    const int Erx = in_sizes[7];
    const int Etot = Exx + Ecx + Erx;

    float *agg, *txxf, *tcxf, *trxf;
    int *off, *cur, *bsum;
    unsigned int* eidx;
    cudaGetSymbolAddress((void**)&agg,  g_agg);
    cudaGetSymbolAddress((void**)&txxf, g_txx);
    cudaGetSymbolAddress((void**)&tcxf, g_tcx);
    cudaGetSymbolAddress((void**)&trxf, g_trx);
    cudaGetSymbolAddress((void**)&off,  g_off);
    cudaGetSymbolAddress((void**)&cur,  g_cur);
    cudaGetSymbolAddress((void**)&bsum, g_bsum);
    cudaGetSymbolAddress((void**)&eidx, g_eidx);
    __half* txx = (__half*)txxf;
    __half* tcx = (__half*)tcxf;
    __half* trx = (__half*)trxf;

    float* out   = (float*)d_out;
    float* x_out = out;
    float* c_out = out + (size_t)nx * 64;
    float* r_out = out + (size_t)nx * 64 + (size_t)nc * 64;

    const int gx = (nx + 127) / 128;
    const int gc = (nc + 127) / 128;
    const int gr = (nr + 127) / 128;
    const int nb = (nx + 1023) / 1024;

    // one-time (first, uncaptured correctness call) side-stream + events
    static cudaStream_t s_side = nullptr;
    static cudaEvent_t  ev_fork = nullptr, ev_join = nullptr;
    if (s_side == nullptr) {
        cudaStreamCreateWithFlags(&s_side, cudaStreamNonBlocking);
        cudaEventCreateWithFlags(&ev_fork, cudaEventDisableTiming);
        cudaEventCreateWithFlags(&ev_join, cudaEventDisableTiming);
        cudaFuncSetAttribute((const void*)hmma_gemm_dual<64>,
                             cudaFuncAttributeMaxDynamicSharedMemorySize, SMEM_DU);
        cudaFuncSetAttribute((const void*)hmma_gemm_dual<32>,
                             cudaFuncAttributeMaxDynamicSharedMemorySize, SMEM_DU);
    }

    // ---- fork: CSR build on side stream, GEMMs on main stream ----
    cudaEventRecord(ev_fork, 0);
    cudaStreamWaitEvent(s_side, ev_fork, 0);

    hist_kernel4<<<(Etot / 4 + 256) / 256, 256, 0, s_side>>>(
        e_xx_d, e_cx_d, e_rx_d, Exx, Ecx, Erx, cur);
    scan1_kernel<<<nb, 1024, 0, s_side>>>(cur, off, bsum, nx);
    scan2_kernel<<<1, 128, 0, s_side>>>(bsum, nb, off, nx, Etot);
    scan3_kernel<<<nb, 1024, 0, s_side>>>(off, bsum, cur, nx);
    fill_kernel4<<<(Etot / 4 + 256) / 256, 256, 0, s_side>>>(
        e_xx_s, e_xx_d, e_cx_s, e_cx_d, e_rx_s, e_rx_d,
        Exx, Ecx, Erx, cur, eidx);
    // re-zero cur for next replay (in GEMM shadow, before the join)
    zero_kernel<<<(nx + 255) / 256, 256, 0, s_side>>>(cur, nx);
    gemm_small<48, true, __half><<<gr, 128, 0, s_side>>>(r, nr, W_rx, b_rx, trx);
    gemm_small<48, true, float ><<<gr, 128, 0, s_side>>>(r, nr, W_r,  b_r,  r_out);
    cudaEventRecord(ev_join, s_side);

    // ---- per-node transforms on main stream (overlap with CSR) ----
    hmma_gemm_dual<64><<<gx, 256, SMEM_DU>>>(x, nx, W_x, b_x, agg,
                                             W_xx, b_xx, txx);
    hmma_gemm_dual<32><<<gc, 256, SMEM_DU>>>(c, nc, W_c, b_c, c_out,
                                             W_cx, b_cx, tcx);

    // ---- join: fused gather + pool projection ----
    cudaStreamWaitEvent(0, ev_join, 0);
    gather_pool<<<1184, 256>>>(txx, tcx, trx, agg, off, eidx,
                               W_pool, b_pool, x_out, nx);
}

// round 15
// speedup vs baseline: 1.2033x; 1.2033x over previous
#include <cuda_runtime.h>
#include <cuda_bf16.h>
#include <cuda_fp16.h>
#include <cstdint>

#define NX_MAX 100000
#define NC_MAX 50000
#define NR_MAX 1000
#define HID 64
#define EMAX 4200000

__device__ float g_agg[(size_t)NX_MAX * HID];
__device__ float g_txx[(size_t)NX_MAX * HID / 2];
__device__ float g_tcx[(size_t)NC_MAX * HID / 2];
__device__ float g_trx[(size_t)NR_MAX * HID / 2];
__device__ int   g_off[NX_MAX + 1];
__device__ int   g_cur[NX_MAX];          // zero at load; re-zeroed each call (in-shadow)
__device__ int   g_bsum[256];
__device__ unsigned int g_eidx[EMAX];

// ---------- helpers ----------
__device__ __forceinline__ uint32_t smem_to_u32(const void* p) {
    uint32_t a;
    asm("{ .reg .u64 t; cvta.to.shared.u64 t, %1; cvt.u32.u64 %0, t; }"
        : "=r"(a) : "l"(p));
    return a;
}

__device__ __forceinline__ void split4(const float4 v, unsigned long long& hi,
                                       unsigned long long& lo) {
    __nv_bfloat16 h0 = __float2bfloat16_rn(v.x);
    __nv_bfloat16 h1 = __float2bfloat16_rn(v.y);
    __nv_bfloat16 h2 = __float2bfloat16_rn(v.z);
    __nv_bfloat16 h3 = __float2bfloat16_rn(v.w);
    __nv_bfloat16 l0 = __float2bfloat16_rn(v.x - __bfloat162float(h0));
    __nv_bfloat16 l1 = __float2bfloat16_rn(v.y - __bfloat162float(h1));
    __nv_bfloat16 l2 = __float2bfloat16_rn(v.z - __bfloat162float(h2));
    __nv_bfloat16 l3 = __float2bfloat16_rn(v.w - __bfloat162float(h3));
    __nv_bfloat162 ha = __halves2bfloat162(h0, h1), hb = __halves2bfloat162(h2, h3);
    __nv_bfloat162 la = __halves2bfloat162(l0, l1), lb = __halves2bfloat162(l2, l3);
    hi = (unsigned long long)*reinterpret_cast<uint32_t*>(&ha) |
         ((unsigned long long)*reinterpret_cast<uint32_t*>(&hb) << 32);
    lo = (unsigned long long)*reinterpret_cast<uint32_t*>(&la) |
         ((unsigned long long)*reinterpret_cast<uint32_t*>(&lb) << 32);
}

__device__ __forceinline__ void ldsm_x4(uint32_t* r, uint32_t addr) {
    asm volatile("ldmatrix.sync.aligned.m8n8.x4.shared.b16 {%0,%1,%2,%3}, [%4];"
                 : "=r"(r[0]), "=r"(r[1]), "=r"(r[2]), "=r"(r[3]) : "r"(addr));
}
__device__ __forceinline__ void mma16816(float* c, const uint32_t* a,
                                         uint32_t b0, uint32_t b1) {
    asm volatile(
        "mma.sync.aligned.m16n8k16.row.col.f32.bf16.bf16.f32 "
        "{%0,%1,%2,%3}, {%4,%5,%6,%7}, {%8,%9}, {%0,%1,%2,%3};"
        : "+f"(c[0]), "+f"(c[1]), "+f"(c[2]), "+f"(c[3])
        : "r"(a[0]), "r"(a[1]), "r"(a[2]), "r"(a[3]), "r"(b0), "r"(b1));
}

// ---------------------------------------------------------------------------
// hmma_gemm (single output) — pool projection.
// ---------------------------------------------------------------------------
#define SOFF_AH 0
#define SOFF_AL 16384
#define SOFF_WH 32768
#define SOFF_WL 40960
#define SOFF_BI 49152
#define SMEM_HM 49408

template <int F, bool RELU, typename OUT>
__global__ void __launch_bounds__(256) hmma_gemm(
    const float* __restrict__ X, int N,
    const float* __restrict__ W, const float* __restrict__ B,
    OUT* __restrict__ Y)
{
    constexpr int NG = F / 4;
    constexpr int KS = F / 16;

    extern __shared__ char smem[];
    const uint32_t sb = smem_to_u32(smem);
    const int tid  = threadIdx.x;
    const int wid  = tid >> 5;
    const int lane = tid & 31;
    const int rowBase = blockIdx.x * 128;

    if (tid < 64) *reinterpret_cast<float*>(smem + SOFF_BI + tid * 4) = B[tid];

    {
        const float4* X4 = reinterpret_cast<const float4*>(X);
        for (int i = tid; i < 128 * NG; i += 256) {
            int r = i / NG;
            int g = i - r * NG;
            int row = rowBase + r;
            float4 v = make_float4(0.f, 0.f, 0.f, 0.f);
            if (row < N) v = X4[(size_t)row * NG + g];
            unsigned long long hi, lo;
            split4(v, hi, lo);
            uint32_t off = r * 128 + ((g * 8) ^ ((r & 7) << 4));
            *reinterpret_cast<unsigned long long*>(smem + SOFF_AH + off) = hi;
            *reinterpret_cast<unsigned long long*>(smem + SOFF_AL + off) = lo;
        }
    }
    {
        const float4* W4 = reinterpret_cast<const float4*>(W);
        for (int i = tid; i < 64 * NG; i += 256) {
            int n = i / NG;
            int g = i - n * NG;
            float4 v = W4[(size_t)n * NG + g];
            unsigned long long hi, lo;
            split4(v, hi, lo);
            uint32_t off = n * 128 + ((g * 8) ^ ((n & 7) << 4));
            *reinterpret_cast<unsigned long long*>(smem + SOFF_WH + off) = hi;
            *reinterpret_cast<unsigned long long*>(smem + SOFF_WL + off) = lo;
        }
    }
    __syncthreads();

    const int rA   = wid * 16 + (lane & 7) + ((lane >> 3) & 1) * 8;
    const uint32_t aOff  = ((lane >> 4) & 1) * 16;
    const uint32_t aXor  = (rA & 7) << 4;
    const uint32_t aBaseH = sb + SOFF_AH + rA * 128;
    const uint32_t aBaseL = sb + SOFF_AL + rA * 128;

    uint32_t bBaseH[4], bBaseL[4], bXor[4];
    const uint32_t bOff = ((lane >> 3) & 1) * 16;
#pragma unroll
    for (int p = 0; p < 4; p++) {
        int n = p * 16 + ((lane >> 4) & 1) * 8 + (lane & 7);
        bXor[p]   = (n & 7) << 4;
        bBaseH[p] = sb + SOFF_WH + n * 128;
        bBaseL[p] = sb + SOFF_WL + n * 128;
    }

    float c[8][4];
#pragma unroll
    for (int nt = 0; nt < 8; nt++)
#pragma unroll
        for (int q = 0; q < 4; q++) c[nt][q] = 0.f;

#pragma unroll
    for (int ks = 0; ks < KS; ks++) {
        uint32_t ah[4], al[4];
        ldsm_x4(ah, aBaseH + ((ks * 32 + aOff) ^ aXor));
        ldsm_x4(al, aBaseL + ((ks * 32 + aOff) ^ aXor));
#pragma unroll
        for (int p = 0; p < 4; p++) {
            uint32_t bh[4], bl[4];
            ldsm_x4(bh, bBaseH[p] + ((ks * 32 + bOff) ^ bXor[p]));
            ldsm_x4(bl, bBaseL[p] + ((ks * 32 + bOff) ^ bXor[p]));
            mma16816(c[2 * p],     ah, bh[0], bh[1]);
            mma16816(c[2 * p],     ah, bl[0], bl[1]);
            mma16816(c[2 * p],     al, bh[0], bh[1]);
            mma16816(c[2 * p + 1], ah, bh[2], bh[3]);
            mma16816(c[2 * p + 1], ah, bl[2], bl[3]);
            mma16816(c[2 * p + 1], al, bh[2], bh[3]);
        }
    }

    const int g = lane >> 2;
    const int t = lane & 3;
    const int row0 = rowBase + wid * 16 + g;
    const float* Bs = reinterpret_cast<const float*>(smem + SOFF_BI);
#pragma unroll
    for (int nt = 0; nt < 8; nt++) {
        int col = nt * 8 + 2 * t;
        float bx = Bs[col], by = Bs[col + 1];
        float v0 = c[nt][0] + bx, v1 = c[nt][1] + by;
        float v2 = c[nt][2] + bx, v3 = c[nt][3] + by;
        if (RELU) {
            v0 = fmaxf(v0, 0.f); v1 = fmaxf(v1, 0.f);
            v2 = fmaxf(v2, 0.f); v3 = fmaxf(v3, 0.f);
        }
        if constexpr (sizeof(OUT) == 2) {
            if (row0 < N)
                *reinterpret_cast<__half2*>((__half*)Y + (size_t)row0 * 64 + col) =
                    __floats2half2_rn(v0, v1);
            if (row0 + 8 < N)
                *reinterpret_cast<__half2*>((__half*)Y + (size_t)(row0 + 8) * 64 + col) =
                    __floats2half2_rn(v2, v3);
        } else {
            if (row0 < N)
                *reinterpret_cast<float2*>((float*)Y + (size_t)row0 * 64 + col) =
                    make_float2(v0, v1);
            if (row0 + 8 < N)
                *reinterpret_cast<float2*>((float*)Y + (size_t)(row0 + 8) * 64 + col) =
                    make_float2(v2, v3);
        }
    }
}

// ---------------------------------------------------------------------------
// hmma_gemm_dual: stage A once, two weight sets, two outputs.
// ---------------------------------------------------------------------------
#define D_AH   0
#define D_AL   16384
#define D_W1H  32768
#define D_W1L  40960
#define D_W2H  49152
#define D_W2L  57344
#define D_BI1  65536
#define D_BI2  65792
#define SMEM_DU 66048

template <int F>
__global__ void __launch_bounds__(256, 2) hmma_gemm_dual(
    const float* __restrict__ X, int N,
    const float* __restrict__ W1, const float* __restrict__ B1,
    float* __restrict__ Y1,
    const float* __restrict__ W2, const float* __restrict__ B2,
    __half* __restrict__ Y2)
{
    constexpr int NG = F / 4;
    constexpr int KS = F / 16;

    extern __shared__ char smem[];
    const uint32_t sb = smem_to_u32(smem);
    const int tid  = threadIdx.x;
    const int wid  = tid >> 5;
    const int lane = tid & 31;
    const int rowBase = blockIdx.x * 128;

    if (tid < 64) {
        *reinterpret_cast<float*>(smem + D_BI1 + tid * 4) = B1[tid];
        *reinterpret_cast<float*>(smem + D_BI2 + tid * 4) = B2[tid];
    }

    {
        const float4* X4 = reinterpret_cast<const float4*>(X);
        for (int i = tid; i < 128 * NG; i += 256) {
            int r = i / NG;
            int g = i - r * NG;
            int row = rowBase + r;
            float4 v = make_float4(0.f, 0.f, 0.f, 0.f);
            if (row < N) v = X4[(size_t)row * NG + g];
            unsigned long long hi, lo;
            split4(v, hi, lo);
            uint32_t off = r * 128 + ((g * 8) ^ ((r & 7) << 4));
            *reinterpret_cast<unsigned long long*>(smem + D_AH + off) = hi;
            *reinterpret_cast<unsigned long long*>(smem + D_AL + off) = lo;
        }
    }
    {
        const float4* W14 = reinterpret_cast<const float4*>(W1);
        const float4* W24 = reinterpret_cast<const float4*>(W2);
        for (int i = tid; i < 64 * NG; i += 256) {
            int n = i / NG;
            int g = i - n * NG;
            uint32_t off = n * 128 + ((g * 8) ^ ((n & 7) << 4));
            {
                float4 v = W14[(size_t)n * NG + g];
                unsigned long long hi, lo;
                split4(v, hi, lo);
                *reinterpret_cast<unsigned long long*>(smem + D_W1H + off) = hi;
                *reinterpret_cast<unsigned long long*>(smem + D_W1L + off) = lo;
            }
            {
                float4 v = W24[(size_t)n * NG + g];
                unsigned long long hi, lo;
                split4(v, hi, lo);
                *reinterpret_cast<unsigned long long*>(smem + D_W2H + off) = hi;
                *reinterpret_cast<unsigned long long*>(smem + D_W2L + off) = lo;
            }
        }
    }
    __syncthreads();

    const int rA   = wid * 16 + (lane & 7) + ((lane >> 3) & 1) * 8;
    const uint32_t aOff  = ((lane >> 4) & 1) * 16;
    const uint32_t aXor  = (rA & 7) << 4;
    const uint32_t aBaseH = sb + D_AH + rA * 128;
    const uint32_t aBaseL = sb + D_AL + rA * 128;

    uint32_t bRow[4], bXor[4];
    const uint32_t bOff = ((lane >> 3) & 1) * 16;
#pragma unroll
    for (int p = 0; p < 4; p++) {
        int n = p * 16 + ((lane >> 4) & 1) * 8 + (lane & 7);
        bXor[p] = (n & 7) << 4;
        bRow[p] = n * 128;
    }

    float c1[8][4], c2[8][4];
#pragma unroll
    for (int nt = 0; nt < 8; nt++)
#pragma unroll
        for (int q = 0; q < 4; q++) { c1[nt][q] = 0.f; c2[nt][q] = 0.f; }

#pragma unroll
    for (int ks = 0; ks < KS; ks++) {
        uint32_t ah[4], al[4];
        ldsm_x4(ah, aBaseH + ((ks * 32 + aOff) ^ aXor));
        ldsm_x4(al, aBaseL + ((ks * 32 + aOff) ^ aXor));
#pragma unroll
        for (int p = 0; p < 4; p++) {
            const uint32_t ko = (ks * 32 + bOff) ^ bXor[p];
            {
                uint32_t bh[4], bl[4];
                ldsm_x4(bh, sb + D_W1H + bRow[p] + ko);
                ldsm_x4(bl, sb + D_W1L + bRow[p] + ko);
                mma16816(c1[2 * p],     ah, bh[0], bh[1]);
                mma16816(c1[2 * p],     ah, bl[0], bl[1]);
                mma16816(c1[2 * p],     al, bh[0], bh[1]);
                mma16816(c1[2 * p + 1], ah, bh[2], bh[3]);
                mma16816(c1[2 * p + 1], ah, bl[2], bl[3]);
                mma16816(c1[2 * p + 1], al, bh[2], bh[3]);
            }
            {
                uint32_t bh[4], bl[4];
                ldsm_x4(bh, sb + D_W2H + bRow[p] + ko);
                ldsm_x4(bl, sb + D_W2L + bRow[p] + ko);
                mma16816(c2[2 * p],     ah, bh[0], bh[1]);
                mma16816(c2[2 * p],     ah, bl[0], bl[1]);
                mma16816(c2[2 * p],     al, bh[0], bh[1]);
                mma16816(c2[2 * p + 1], ah, bh[2], bh[3]);
                mma16816(c2[2 * p + 1], ah, bl[2], bl[3]);
                mma16816(c2[2 * p + 1], al, bh[2], bh[3]);
            }
        }
    }

    const int g = lane >> 2;
    const int t = lane & 3;
    const int row0 = rowBase + wid * 16 + g;
    const float* Bs1 = reinterpret_cast<const float*>(smem + D_BI1);
    const float* Bs2 = reinterpret_cast<const float*>(smem + D_BI2);
#pragma unroll
    for (int nt = 0; nt < 8; nt++) {
        int col = nt * 8 + 2 * t;
        {
            float bx = Bs1[col], by = Bs1[col + 1];
            float v0 = fmaxf(c1[nt][0] + bx, 0.f), v1 = fmaxf(c1[nt][1] + by, 0.f);
            float v2 = fmaxf(c1[nt][2] + bx, 0.f), v3 = fmaxf(c1[nt][3] + by, 0.f);
            if (row0 < N)
                *reinterpret_cast<float2*>(Y1 + (size_t)row0 * 64 + col) =
                    make_float2(v0, v1);
            if (row0 + 8 < N)
                *reinterpret_cast<float2*>(Y1 + (size_t)(row0 + 8) * 64 + col) =
                    make_float2(v2, v3);
        }
        {
            float bx = Bs2[col], by = Bs2[col + 1];
            float v0 = fmaxf(c2[nt][0] + bx, 0.f), v1 = fmaxf(c2[nt][1] + by, 0.f);
            float v2 = fmaxf(c2[nt][2] + bx, 0.f), v3 = fmaxf(c2[nt][3] + by, 0.f);
            if (row0 < N)
                *reinterpret_cast<__half2*>(Y2 + (size_t)row0 * 64 + col) =
                    __floats2half2_rn(v0, v1);
            if (row0 + 8 < N)
                *reinterpret_cast<__half2*>(Y2 + (size_t)(row0 + 8) * 64 + col) =
                    __floats2half2_rn(v2, v3);
        }
    }
}

// ---------------- small GEMM for r (F=48, N=1000) ----------------
template <int F, bool RELU, typename OUT>
__global__ void __launch_bounds__(128) gemm_small(
    const float* __restrict__ X, int N,
    const float* __restrict__ W, const float* __restrict__ B,
    OUT* __restrict__ Y)
{
    __shared__ float Wt[F * 64];
    __shared__ float Bs[64];
    const int tid = threadIdx.x;
    for (int i = tid; i < F * 64; i += 128) {
        int j = i / F;
        int k = i - j * F;
        Wt[k * 64 + j] = W[i];
    }
    if (tid < 64) Bs[tid] = B[tid];
    __syncthreads();
    const int row = blockIdx.x * 128 + tid;
    if (row >= N) return;
    float4 acc[16];
    const float4* Bs4 = reinterpret_cast<const float4*>(Bs);
#pragma unroll
    for (int j = 0; j < 16; j++) acc[j] = Bs4[j];
    const float4* X4  = reinterpret_cast<const float4*>(X + (size_t)row * F);
    const float4* Wt4 = reinterpret_cast<const float4*>(Wt);
#pragma unroll 2
    for (int k4 = 0; k4 < F / 4; k4++) {
        const float4 xv = X4[k4];
#pragma unroll
        for (int kk = 0; kk < 4; kk++) {
            const float xs = (kk == 0) ? xv.x : (kk == 1) ? xv.y : (kk == 2) ? xv.z : xv.w;
            const float4* wrow = Wt4 + (size_t)(k4 * 4 + kk) * 16;
#pragma unroll
            for (int j = 0; j < 16; j++) {
                float4 w = wrow[j];
                acc[j].x += xs * w.x; acc[j].y += xs * w.y;
                acc[j].z += xs * w.z; acc[j].w += xs * w.w;
            }
        }
    }
#pragma unroll
    for (int j = 0; j < 16; j++) {
        float4 v = acc[j];
        if (RELU) {
            v.x = fmaxf(v.x, 0.f); v.y = fmaxf(v.y, 0.f);
            v.z = fmaxf(v.z, 0.f); v.w = fmaxf(v.w, 0.f);
        }
        if constexpr (sizeof(OUT) == 2) {
            __half2* p = reinterpret_cast<__half2*>((__half*)Y + (size_t)row * 64 + j * 4);
            p[0] = __floats2half2_rn(v.x, v.y);
            p[1] = __floats2half2_rn(v.z, v.w);
        } else {
            reinterpret_cast<float4*>((float*)Y + (size_t)row * 64)[j] = v;
        }
    }
}

// ---------------- CSR build ----------------
__global__ void zero_kernel(int* p, int n) {
    int i = blockIdx.x * blockDim.x + threadIdx.x;
    if (i < n) p[i] = 0;
}

__global__ void hist_kernel4(const int* __restrict__ dxx, const int* __restrict__ dcx,
                             const int* __restrict__ drx,
                             int Exx, int Ecx, int Erx, int* __restrict__ deg)
{
    int base = (blockIdx.x * blockDim.x + threadIdx.x) * 4;
    int Etot = Exx + Ecx + Erx;
    int d[4];
    int cnt = 0;
#pragma unroll
    for (int j = 0; j < 4; j++) {
        int i = base + j;
        if (i < Etot) {
            if (i < Exx) d[cnt] = dxx[i];
            else if (i < Exx + Ecx) d[cnt] = dcx[i - Exx];
            else d[cnt] = drx[i - Exx - Ecx];
            cnt++;
        }
    }
#pragma unroll
    for (int j = 0; j < 4; j++)
        if (j < cnt) atomicAdd(&deg[d[j]], 1);
}

__global__ void scan1_kernel(const int* __restrict__ deg, int* __restrict__ off,
                             int* __restrict__ bsum, int n)
{
    __shared__ int s[1024];
    int t = threadIdx.x;
    int i = blockIdx.x * 1024 + t;
    int v = (i < n) ? deg[i] : 0;
    s[t] = v;
    __syncthreads();
#pragma unroll
    for (int o = 1; o < 1024; o <<= 1) {
        int a = (t >= o) ? s[t - o] : 0;
        __syncthreads();
        s[t] += a;
        __syncthreads();
    }
    if (i < n) off[i] = s[t] - v;
    if (t == 1023) bsum[blockIdx.x] = s[1023];
}

__global__ void scan2_kernel(int* __restrict__ bsum, int nb, int* __restrict__ off,
                             int n, int Etot)
{
    __shared__ int s[128];
    int t = threadIdx.x;
    int v = (t < nb) ? bsum[t] : 0;
    s[t] = v;
    __syncthreads();
#pragma unroll
    for (int o = 1; o < 128; o <<= 1) {
        int a = (t >= o) ? s[t - o] : 0;
        __syncthreads();
        s[t] += a;
        __syncthreads();
    }
    if (t < nb) bsum[t] = s[t] - v;
    if (t == 0) off[n] = Etot;
}

__global__ void scan3_kernel(int* __restrict__ off, const int* __restrict__ bsum,
                             int* __restrict__ cur, int n)
{
    int i = blockIdx.x * 1024 + threadIdx.x;
    if (i < n) {
        int o = off[i] + bsum[blockIdx.x];
        off[i] = o;
        cur[i] = o;
    }
}

__global__ void fill_kernel4(const int* __restrict__ sxx, const int* __restrict__ dxx,
                             const int* __restrict__ scx, const int* __restrict__ dcx,
                             const int* __restrict__ srx, const int* __restrict__ drx,
                             int Exx, int Ecx, int Erx,
                             int* __restrict__ cur, unsigned int* __restrict__ eidx)
{
    int base = (blockIdx.x * blockDim.x + threadIdx.x) * 4;
    int Etot = Exx + Ecx + Erx;
    int d[4]; unsigned int rec[4];
    int cnt = 0;
#pragma unroll
    for (int j = 0; j < 4; j++) {
        int i = base + j;
        if (i < Etot) {
            int dd, ss; unsigned int rel;
            if (i < Exx)            { dd = dxx[i];             ss = sxx[i];             rel = 0u; }
            else if (i < Exx + Ecx) { dd = dcx[i - Exx];       ss = scx[i - Exx];       rel = 1u; }
            else                    { dd = drx[i - Exx - Ecx]; ss = srx[i - Exx - Ecx]; rel = 2u; }
            d[cnt] = dd;
            rec[cnt] = (rel << 28) | (unsigned int)ss;
            cnt++;
        }
    }
#pragma unroll
    for (int j = 0; j < 4; j++) {
        if (j < cnt) {
            int p = atomicAdd(&cur[d[j]], 1);
            eidx[p] = rec[j];
        }
    }
}

// ---------------------------------------------------------------------------
// gather-accumulate v4 (row-range version): 8 lanes/edge (uint4),
// 32-edge main loop (MLP=8/lane)
// ---------------------------------------------------------------------------
__device__ __forceinline__ void acc8h(float4& a0, float4& a1,
                                      const __half* __restrict__ txx,
                                      const __half* __restrict__ tcx,
                                      const __half* __restrict__ trx,
                                      unsigned int rr, int q)
{
    const __half* t = (rr >> 28) == 0 ? txx : ((rr >> 28) == 1 ? tcx : trx);
    uint4 h = *reinterpret_cast<const uint4*>(
        t + (size_t)(rr & 0x0FFFFFFFu) * 64 + q * 8);
    const __half2* hp = reinterpret_cast<const __half2*>(&h);
    float2 f0 = __half22float2(hp[0]);
    float2 f1 = __half22float2(hp[1]);
    float2 f2 = __half22float2(hp[2]);
    float2 f3 = __half22float2(hp[3]);
    a0.x += f0.x; a0.y += f0.y; a0.z += f1.x; a0.w += f1.y;
    a1.x += f2.x; a1.y += f2.y; a1.z += f3.x; a1.w += f3.y;
}

__global__ void __launch_bounds__(256) gather_accum_v4(
    const __half* __restrict__ txx, const __half* __restrict__ tcx,
    const __half* __restrict__ trx,
    float* __restrict__ agg,
    const int* __restrict__ off, const unsigned int* __restrict__ eidx,
    int rowStart, int rowEnd)
{
    const int warp = rowStart + ((blockIdx.x * 256 + threadIdx.x) >> 5);
    const int lane = threadIdx.x & 31;
    if (warp >= rowEnd) return;
    const int quarter = lane >> 3;
    const int q       = lane & 7;
    const int s = off[warp];
    const int e = off[warp + 1];

    float4 a0 = make_float4(0.f, 0.f, 0.f, 0.f);
    float4 a1 = make_float4(0.f, 0.f, 0.f, 0.f);

    int i = s;
    for (; i + 32 <= e; i += 32) {
        unsigned int r0 = eidx[i      + quarter];
        unsigned int r1 = eidx[i + 4  + quarter];
        unsigned int r2 = eidx[i + 8  + quarter];
        unsigned int r3 = eidx[i + 12 + quarter];
        unsigned int r4 = eidx[i + 16 + quarter];
        unsigned int r5 = eidx[i + 20 + quarter];
        unsigned int r6 = eidx[i + 24 + quarter];
        unsigned int r7 = eidx[i + 28 + quarter];
        acc8h(a0, a1, txx, tcx, trx, r0, q);
        acc8h(a0, a1, txx, tcx, trx, r1, q);
        acc8h(a0, a1, txx, tcx, trx, r2, q);
        acc8h(a0, a1, txx, tcx, trx, r3, q);
        acc8h(a0, a1, txx, tcx, trx, r4, q);
        acc8h(a0, a1, txx, tcx, trx, r5, q);
        acc8h(a0, a1, txx, tcx, trx, r6, q);
        acc8h(a0, a1, txx, tcx, trx, r7, q);
    }
    for (; i + 16 <= e; i += 16) {
        unsigned int r0 = eidx[i      + quarter];
        unsigned int r1 = eidx[i + 4  + quarter];
        unsigned int r2 = eidx[i + 8  + quarter];
        unsigned int r3 = eidx[i + 12 + quarter];
        acc8h(a0, a1, txx, tcx, trx, r0, q);
        acc8h(a0, a1, txx, tcx, trx, r1, q);
        acc8h(a0, a1, txx, tcx, trx, r2, q);
        acc8h(a0, a1, txx, tcx, trx, r3, q);
    }
    for (; i + 4 <= e; i += 4) {
        acc8h(a0, a1, txx, tcx, trx, eidx[i + quarter], q);
    }
    if (quarter < e - i) {
        acc8h(a0, a1, txx, tcx, trx, eidx[i + quarter], q);
    }

#pragma unroll
    for (int m = 8; m <= 16; m <<= 1) {
        a0.x += __shfl_xor_sync(0xFFFFFFFFu, a0.x, m);
        a0.y += __shfl_xor_sync(0xFFFFFFFFu, a0.y, m);
        a0.z += __shfl_xor_sync(0xFFFFFFFFu, a0.z, m);
        a0.w += __shfl_xor_sync(0xFFFFFFFFu, a0.w, m);
        a1.x += __shfl_xor_sync(0xFFFFFFFFu, a1.x, m);
        a1.y += __shfl_xor_sync(0xFFFFFFFFu, a1.y, m);
        a1.z += __shfl_xor_sync(0xFFFFFFFFu, a1.z, m);
        a1.w += __shfl_xor_sync(0xFFFFFFFFu, a1.w, m);
    }

    if (quarter == 0) {
        float4* p = reinterpret_cast<float4*>(agg + (size_t)warp * 64 + q * 8);
        float4 b0 = p[0], b1 = p[1];
        b0.x += a0.x; b0.y += a0.y; b0.z += a0.z; b0.w += a0.w;
        b1.x += a1.x; b1.y += a1.y; b1.z += a1.z; b1.w += a1.w;
        p[0] = b0;
        p[1] = b1;
    }
}

extern "C" void kernel_launch(void* const* d_in, const int* in_sizes, int n_in,
                              void* d_out, int out_size)
{
    const float* x      = (const float*)d_in[0];
    const float* c      = (const float*)d_in[1];
    const float* r      = (const float*)d_in[2];
    const int*   e_xx_s = (const int*)d_in[3];
    const int*   e_xx_d = (const int*)d_in[4];
    const int*   e_cx_s = (const int*)d_in[5];
    const int*   e_cx_d = (const int*)d_in[6];
    const int*   e_rx_s = (const int*)d_in[7];
    const int*   e_rx_d = (const int*)d_in[8];
    const float* W_x    = (const float*)d_in[9];
    const float* b_x    = (const float*)d_in[10];
    const float* W_c    = (const float*)d_in[11];
    const float* b_c    = (const float*)d_in[12];
    const float* W_r    = (const float*)d_in[13];
    const float* b_r    = (const float*)d_in[14];
    const float* W_xx   = (const float*)d_in[15];
    const float* b_xx   = (const float*)d_in[16];
    const float* W_cx   = (const float*)d_in[17];
    const float* b_cx   = (const float*)d_in[18];
    const float* W_rx   = (const float*)d_in[19];
    const float* b_rx   = (const float*)d_in[20];
    const float* W_pool = (const float*)d_in[21];
    const float* b_pool = (const float*)d_in[22];

    const int nx  = in_sizes[0] / 64;
    const int nc  = in_sizes[1] / 32;
    const int nr  = in_sizes[2] / 48;
    const int Exx = in_sizes[3];
    const int Ecx = in_sizes[5];
    const int Erx = in_sizes[7];
    const int Etot = Exx + Ecx + Erx;

    float *agg, *txxf, *tcxf, *trxf;
    int *off, *cur, *bsum;
    unsigned int* eidx;
    cudaGetSymbolAddress((void**)&agg,  g_agg);
    cudaGetSymbolAddress((void**)&txxf, g_txx);
    cudaGetSymbolAddress((void**)&tcxf, g_tcx);
    cudaGetSymbolAddress((void**)&trxf, g_trx);
    cudaGetSymbolAddress((void**)&off,  g_off);
    cudaGetSymbolAddress((void**)&cur,  g_cur);
    cudaGetSymbolAddress((void**)&bsum, g_bsum);
    cudaGetSymbolAddress((void**)&eidx, g_eidx);
    __half* txx = (__half*)txxf;
    __half* tcx = (__half*)tcxf;
    __half* trx = (__half*)trxf;

    float* out   = (float*)d_out;
    float* x_out = out;
    float* c_out = out + (size_t)nx * 64;
    float* r_out = out + (size_t)nx * 64 + (size_t)nc * 64;

    const int gx = (nx + 127) / 128;
    const int gc = (nc + 127) / 128;
    const int gr = (nr + 127) / 128;
    const int nb = (nx + 1023) / 1024;

    // row split for gather/pool pipelining (multiple of 128)
    const int gx1   = gx / 2;            // tiles in first half
    const int half  = gx1 * 128;         // rows in first half
    const int gx2   = gx - gx1;

    // one-time (first, uncaptured correctness call) side-stream + events
    static cudaStream_t s_side = nullptr;
    static cudaEvent_t  ev_fork = nullptr, ev_join = nullptr;
    static cudaEvent_t  ev_g1 = nullptr, ev_p1 = nullptr;
    if (s_side == nullptr) {
        cudaStreamCreateWithFlags(&s_side, cudaStreamNonBlocking);
        cudaEventCreateWithFlags(&ev_fork, cudaEventDisableTiming);
        cudaEventCreateWithFlags(&ev_join, cudaEventDisableTiming);
        cudaEventCreateWithFlags(&ev_g1,   cudaEventDisableTiming);
        cudaEventCreateWithFlags(&ev_p1,   cudaEventDisableTiming);
        cudaFuncSetAttribute((const void*)hmma_gemm_dual<64>,
                             cudaFuncAttributeMaxDynamicSharedMemorySize, SMEM_DU);
        cudaFuncSetAttribute((const void*)hmma_gemm_dual<32>,
                             cudaFuncAttributeMaxDynamicSharedMemorySize, SMEM_DU);
        cudaFuncSetAttribute((const void*)hmma_gemm<64, false, float>,
                             cudaFuncAttributeMaxDynamicSharedMemorySize, SMEM_HM);
    }

    // ---- fork: CSR build on side stream, GEMMs on main stream ----
    cudaEventRecord(ev_fork, 0);
    cudaStreamWaitEvent(s_side, ev_fork, 0);

    hist_kernel4<<<(Etot / 4 + 256) / 256, 256, 0, s_side>>>(
        e_xx_d, e_cx_d, e_rx_d, Exx, Ecx, Erx, cur);
    scan1_kernel<<<nb, 1024, 0, s_side>>>(cur, off, bsum, nx);
    scan2_kernel<<<1, 128, 0, s_side>>>(bsum, nb, off, nx, Etot);
    scan3_kernel<<<nb, 1024, 0, s_side>>>(off, bsum, cur, nx);
    fill_kernel4<<<(Etot / 4 + 256) / 256, 256, 0, s_side>>>(
        e_xx_s, e_xx_d, e_cx_s, e_cx_d, e_rx_s, e_rx_d,
        Exx, Ecx, Erx, cur, eidx);
    zero_kernel<<<(nx + 255) / 256, 256, 0, s_side>>>(cur, nx);
    gemm_small<48, true, __half><<<gr, 128, 0, s_side>>>(r, nr, W_rx, b_rx, trx);
    gemm_small<48, true, float ><<<gr, 128, 0, s_side>>>(r, nr, W_r,  b_r,  r_out);
    cudaEventRecord(ev_join, s_side);

    // ---- per-node transforms on main stream (overlap with CSR) ----
    hmma_gemm_dual<64><<<gx, 256, SMEM_DU>>>(x, nx, W_x, b_x, agg,
                                             W_xx, b_xx, txx);
    hmma_gemm_dual<32><<<gc, 256, SMEM_DU>>>(c, nc, W_c, b_c, c_out,
                                             W_cx, b_cx, tcx);

    // ---- join + pipelined gather/pool ----
    cudaStreamWaitEvent(0, ev_join, 0);

    // gather first half, signal side stream
    gather_accum_v4<<<(half + 7) / 8, 256>>>(txx, tcx, trx, agg, off, eidx,
                                             0, half);
    cudaEventRecord(ev_g1, 0);
    cudaStreamWaitEvent(s_side, ev_g1, 0);

    // pool first half on side stream (overlaps second gather)
    hmma_gemm<64, false, float><<<gx1, 256, SMEM_HM, s_side>>>(
        agg, half, W_pool, b_pool, x_out);
    cudaEventRecord(ev_p1, s_side);

    // gather second half on main
    gather_accum_v4<<<(nx - half + 7) / 8, 256>>>(txx, tcx, trx, agg, off, eidx,
                                                  half, nx);

    // pool second half on main
    hmma_gemm<64, false, float><<<gx2, 256, SMEM_HM>>>(
        agg + (size_t)half * 64, nx - half, W_pool, b_pool,
        x_out + (size_t)half * 64);

    // join side stream before capture ends
    cudaStreamWaitEvent(0, ev_p1, 0);
}

// round 16
// speedup vs baseline: 1.2595x; 1.0467x over previous
#include <cuda_runtime.h>
#include <cuda_bf16.h>
#include <cuda_fp16.h>
#include <cstdint>

#define NX_MAX 100000
#define NC_MAX 50000
#define NR_MAX 1000
#define HID 64
#define EMAX 4200000

__device__ float g_agg[(size_t)NX_MAX * HID];
__device__ float g_txx[(size_t)NX_MAX * HID / 2];
__device__ float g_tcx[(size_t)NC_MAX * HID / 2];
__device__ float g_trx[(size_t)NR_MAX * HID / 2];
__device__ int   g_off[NX_MAX + 1];
__device__ int   g_cur[NX_MAX];          // zero at load; re-zeroed each call (in-shadow)
__device__ int   g_bsum[256];
__device__ unsigned int g_eidx[EMAX];

// ---------- helpers ----------
__device__ __forceinline__ uint32_t smem_to_u32(const void* p) {
    uint32_t a;
    asm("{ .reg .u64 t; cvta.to.shared.u64 t, %1; cvt.u32.u64 %0, t; }"
        : "=r"(a) : "l"(p));
    return a;
}

__device__ __forceinline__ void split4(const float4 v, unsigned long long& hi,
                                       unsigned long long& lo) {
    __nv_bfloat16 h0 = __float2bfloat16_rn(v.x);
    __nv_bfloat16 h1 = __float2bfloat16_rn(v.y);
    __nv_bfloat16 h2 = __float2bfloat16_rn(v.z);
    __nv_bfloat16 h3 = __float2bfloat16_rn(v.w);
    __nv_bfloat16 l0 = __float2bfloat16_rn(v.x - __bfloat162float(h0));
    __nv_bfloat16 l1 = __float2bfloat16_rn(v.y - __bfloat162float(h1));
    __nv_bfloat16 l2 = __float2bfloat16_rn(v.z - __bfloat162float(h2));
    __nv_bfloat16 l3 = __float2bfloat16_rn(v.w - __bfloat162float(h3));
    __nv_bfloat162 ha = __halves2bfloat162(h0, h1), hb = __halves2bfloat162(h2, h3);
    __nv_bfloat162 la = __halves2bfloat162(l0, l1), lb = __halves2bfloat162(l2, l3);
    hi = (unsigned long long)*reinterpret_cast<uint32_t*>(&ha) |
         ((unsigned long long)*reinterpret_cast<uint32_t*>(&hb) << 32);
    lo = (unsigned long long)*reinterpret_cast<uint32_t*>(&la) |
         ((unsigned long long)*reinterpret_cast<uint32_t*>(&lb) << 32);
}

__device__ __forceinline__ void ldsm_x4(uint32_t* r, uint32_t addr) {
    asm volatile("ldmatrix.sync.aligned.m8n8.x4.shared.b16 {%0,%1,%2,%3}, [%4];"
                 : "=r"(r[0]), "=r"(r[1]), "=r"(r[2]), "=r"(r[3]) : "r"(addr));
}
__device__ __forceinline__ void mma16816(float* c, const uint32_t* a,
                                         uint32_t b0, uint32_t b1) {
    asm volatile(
        "mma.sync.aligned.m16n8k16.row.col.f32.bf16.bf16.f32 "
        "{%0,%1,%2,%3}, {%4,%5,%6,%7}, {%8,%9}, {%0,%1,%2,%3};"
        : "+f"(c[0]), "+f"(c[1]), "+f"(c[2]), "+f"(c[3])
        : "r"(a[0]), "r"(a[1]), "r"(a[2]), "r"(a[3]), "r"(b0), "r"(b1));
}

// ---------------------------------------------------------------------------
// hmma_gemm (single output) — pool projection. min 3 CTAs/SM for occupancy.
// ---------------------------------------------------------------------------
#define SOFF_AH 0
#define SOFF_AL 16384
#define SOFF_WH 32768
#define SOFF_WL 40960
#define SOFF_BI 49152
#define SMEM_HM 49408

template <int F, bool RELU, typename OUT>
__global__ void __launch_bounds__(256, 3) hmma_gemm(
    const float* __restrict__ X, int N,
    const float* __restrict__ W, const float* __restrict__ B,
    OUT* __restrict__ Y)
{
    constexpr int NG = F / 4;
    constexpr int KS = F / 16;

    extern __shared__ char smem[];
    const uint32_t sb = smem_to_u32(smem);
    const int tid  = threadIdx.x;
    const int wid  = tid >> 5;
    const int lane = tid & 31;
    const int rowBase = blockIdx.x * 128;

    if (tid < 64) *reinterpret_cast<float*>(smem + SOFF_BI + tid * 4) = B[tid];

    {
        const float4* X4 = reinterpret_cast<const float4*>(X);
        for (int i = tid; i < 128 * NG; i += 256) {
            int r = i / NG;
            int g = i - r * NG;
            int row = rowBase + r;
            float4 v = make_float4(0.f, 0.f, 0.f, 0.f);
            if (row < N) v = X4[(size_t)row * NG + g];
            unsigned long long hi, lo;
            split4(v, hi, lo);
            uint32_t off = r * 128 + ((g * 8) ^ ((r & 7) << 4));
            *reinterpret_cast<unsigned long long*>(smem + SOFF_AH + off) = hi;
            *reinterpret_cast<unsigned long long*>(smem + SOFF_AL + off) = lo;
        }
    }
    {
        const float4* W4 = reinterpret_cast<const float4*>(W);
        for (int i = tid; i < 64 * NG; i += 256) {
            int n = i / NG;
            int g = i - n * NG;
            float4 v = W4[(size_t)n * NG + g];
            unsigned long long hi, lo;
            split4(v, hi, lo);
            uint32_t off = n * 128 + ((g * 8) ^ ((n & 7) << 4));
            *reinterpret_cast<unsigned long long*>(smem + SOFF_WH + off) = hi;
            *reinterpret_cast<unsigned long long*>(smem + SOFF_WL + off) = lo;
        }
    }
    __syncthreads();

    const int rA   = wid * 16 + (lane & 7) + ((lane >> 3) & 1) * 8;
    const uint32_t aOff  = ((lane >> 4) & 1) * 16;
    const uint32_t aXor  = (rA & 7) << 4;
    const uint32_t aBaseH = sb + SOFF_AH + rA * 128;
    const uint32_t aBaseL = sb + SOFF_AL + rA * 128;

    uint32_t bBaseH[4], bBaseL[4], bXor[4];
    const uint32_t bOff = ((lane >> 3) & 1) * 16;
#pragma unroll
    for (int p = 0; p < 4; p++) {
        int n = p * 16 + ((lane >> 4) & 1) * 8 + (lane & 7);
        bXor[p]   = (n & 7) << 4;
        bBaseH[p] = sb + SOFF_WH + n * 128;
        bBaseL[p] = sb + SOFF_WL + n * 128;
    }

    float c[8][4];
#pragma unroll
    for (int nt = 0; nt < 8; nt++)
#pragma unroll
        for (int q = 0; q < 4; q++) c[nt][q] = 0.f;

#pragma unroll
    for (int ks = 0; ks < KS; ks++) {
        uint32_t ah[4], al[4];
        ldsm_x4(ah, aBaseH + ((ks * 32 + aOff) ^ aXor));
        ldsm_x4(al, aBaseL + ((ks * 32 + aOff) ^ aXor));
#pragma unroll
        for (int p = 0; p < 4; p++) {
            uint32_t bh[4], bl[4];
            ldsm_x4(bh, bBaseH[p] + ((ks * 32 + bOff) ^ bXor[p]));
            ldsm_x4(bl, bBaseL[p] + ((ks * 32 + bOff) ^ bXor[p]));
            mma16816(c[2 * p],     ah, bh[0], bh[1]);
            mma16816(c[2 * p],     ah, bl[0], bl[1]);
            mma16816(c[2 * p],     al, bh[0], bh[1]);
            mma16816(c[2 * p + 1], ah, bh[2], bh[3]);
            mma16816(c[2 * p + 1], ah, bl[2], bl[3]);
            mma16816(c[2 * p + 1], al, bh[2], bh[3]);
        }
    }

    const int g = lane >> 2;
    const int t = lane & 3;
    const int row0 = rowBase + wid * 16 + g;
    const float* Bs = reinterpret_cast<const float*>(smem + SOFF_BI);
#pragma unroll
    for (int nt = 0; nt < 8; nt++) {
        int col = nt * 8 + 2 * t;
        float bx = Bs[col], by = Bs[col + 1];
        float v0 = c[nt][0] + bx, v1 = c[nt][1] + by;
        float v2 = c[nt][2] + bx, v3 = c[nt][3] + by;
        if (RELU) {
            v0 = fmaxf(v0, 0.f); v1 = fmaxf(v1, 0.f);
            v2 = fmaxf(v2, 0.f); v3 = fmaxf(v3, 0.f);
        }
        if constexpr (sizeof(OUT) == 2) {
            if (row0 < N)
                *reinterpret_cast<__half2*>((__half*)Y + (size_t)row0 * 64 + col) =
                    __floats2half2_rn(v0, v1);
            if (row0 + 8 < N)
                *reinterpret_cast<__half2*>((__half*)Y + (size_t)(row0 + 8) * 64 + col) =
                    __floats2half2_rn(v2, v3);
        } else {
            if (row0 < N)
                *reinterpret_cast<float2*>((float*)Y + (size_t)row0 * 64 + col) =
                    make_float2(v0, v1);
            if (row0 + 8 < N)
                *reinterpret_cast<float2*>((float*)Y + (size_t)(row0 + 8) * 64 + col) =
                    make_float2(v2, v3);
        }
    }
}

// ---------------------------------------------------------------------------
// hmma_gemm_dual: stage A once, two weight sets, two outputs.
// ---------------------------------------------------------------------------
#define D_AH   0
#define D_AL   16384
#define D_W1H  32768
#define D_W1L  40960
#define D_W2H  49152
#define D_W2L  57344
#define D_BI1  65536
#define D_BI2  65792
#define SMEM_DU 66048

template <int F>
__global__ void __launch_bounds__(256, 2) hmma_gemm_dual(
    const float* __restrict__ X, int N,
    const float* __restrict__ W1, const float* __restrict__ B1,
    float* __restrict__ Y1,
    const float* __restrict__ W2, const float* __restrict__ B2,
    __half* __restrict__ Y2)
{
    constexpr int NG = F / 4;
    constexpr int KS = F / 16;

    extern __shared__ char smem[];
    const uint32_t sb = smem_to_u32(smem);
    const int tid  = threadIdx.x;
    const int wid  = tid >> 5;
    const int lane = tid & 31;
    const int rowBase = blockIdx.x * 128;

    if (tid < 64) {
        *reinterpret_cast<float*>(smem + D_BI1 + tid * 4) = B1[tid];
        *reinterpret_cast<float*>(smem + D_BI2 + tid * 4) = B2[tid];
    }

    {
        const float4* X4 = reinterpret_cast<const float4*>(X);
        for (int i = tid; i < 128 * NG; i += 256) {
            int r = i / NG;
            int g = i - r * NG;
            int row = rowBase + r;
            float4 v = make_float4(0.f, 0.f, 0.f, 0.f);
            if (row < N) v = X4[(size_t)row * NG + g];
            unsigned long long hi, lo;
            split4(v, hi, lo);
            uint32_t off = r * 128 + ((g * 8) ^ ((r & 7) << 4));
            *reinterpret_cast<unsigned long long*>(smem + D_AH + off) = hi;
            *reinterpret_cast<unsigned long long*>(smem + D_AL + off) = lo;
        }
    }
    {
        const float4* W14 = reinterpret_cast<const float4*>(W1);
        const float4* W24 = reinterpret_cast<const float4*>(W2);
        for (int i = tid; i < 64 * NG; i += 256) {
            int n = i / NG;
            int g = i - n * NG;
            uint32_t off = n * 128 + ((g * 8) ^ ((n & 7) << 4));
            {
                float4 v = W14[(size_t)n * NG + g];
                unsigned long long hi, lo;
                split4(v, hi, lo);
                *reinterpret_cast<unsigned long long*>(smem + D_W1H + off) = hi;
                *reinterpret_cast<unsigned long long*>(smem + D_W1L + off) = lo;
            }
            {
                float4 v = W24[(size_t)n * NG + g];
                unsigned long long hi, lo;
                split4(v, hi, lo);
                *reinterpret_cast<unsigned long long*>(smem + D_W2H + off) = hi;
                *reinterpret_cast<unsigned long long*>(smem + D_W2L + off) = lo;
            }
        }
    }
    __syncthreads();

    const int rA   = wid * 16 + (lane & 7) + ((lane >> 3) & 1) * 8;
    const uint32_t aOff  = ((lane >> 4) & 1) * 16;
    const uint32_t aXor  = (rA & 7) << 4;
    const uint32_t aBaseH = sb + D_AH + rA * 128;
    const uint32_t aBaseL = sb + D_AL + rA * 128;

    uint32_t bRow[4], bXor[4];
    const uint32_t bOff = ((lane >> 3) & 1) * 16;
#pragma unroll
    for (int p = 0; p < 4; p++) {
        int n = p * 16 + ((lane >> 4) & 1) * 8 + (lane & 7);
        bXor[p] = (n & 7) << 4;
        bRow[p] = n * 128;
    }

    float c1[8][4], c2[8][4];
#pragma unroll
    for (int nt = 0; nt < 8; nt++)
#pragma unroll
        for (int q = 0; q < 4; q++) { c1[nt][q] = 0.f; c2[nt][q] = 0.f; }

#pragma unroll
    for (int ks = 0; ks < KS; ks++) {
        uint32_t ah[4], al[4];
        ldsm_x4(ah, aBaseH + ((ks * 32 + aOff) ^ aXor));
        ldsm_x4(al, aBaseL + ((ks * 32 + aOff) ^ aXor));
#pragma unroll
        for (int p = 0; p < 4; p++) {
            const uint32_t ko = (ks * 32 + bOff) ^ bXor[p];
            {
                uint32_t bh[4], bl[4];
                ldsm_x4(bh, sb + D_W1H + bRow[p] + ko);
                ldsm_x4(bl, sb + D_W1L + bRow[p] + ko);
                mma16816(c1[2 * p],     ah, bh[0], bh[1]);
                mma16816(c1[2 * p],     ah, bl[0], bl[1]);
                mma16816(c1[2 * p],     al, bh[0], bh[1]);
                mma16816(c1[2 * p + 1], ah, bh[2], bh[3]);
                mma16816(c1[2 * p + 1], ah, bl[2], bl[3]);
                mma16816(c1[2 * p + 1], al, bh[2], bh[3]);
            }
            {
                uint32_t bh[4], bl[4];
                ldsm_x4(bh, sb + D_W2H + bRow[p] + ko);
                ldsm_x4(bl, sb + D_W2L + bRow[p] + ko);
                mma16816(c2[2 * p],     ah, bh[0], bh[1]);
                mma16816(c2[2 * p],     ah, bl[0], bl[1]);
                mma16816(c2[2 * p],     al, bh[0], bh[1]);
                mma16816(c2[2 * p + 1], ah, bh[2], bh[3]);
                mma16816(c2[2 * p + 1], ah, bl[2], bl[3]);
                mma16816(c2[2 * p + 1], al, bh[2], bh[3]);
            }
        }
    }

    const int g = lane >> 2;
    const int t = lane & 3;
    const int row0 = rowBase + wid * 16 + g;
    const float* Bs1 = reinterpret_cast<const float*>(smem + D_BI1);
    const float* Bs2 = reinterpret_cast<const float*>(smem + D_BI2);
#pragma unroll
    for (int nt = 0; nt < 8; nt++) {
        int col = nt * 8 + 2 * t;
        {
            float bx = Bs1[col], by = Bs1[col + 1];
            float v0 = fmaxf(c1[nt][0] + bx, 0.f), v1 = fmaxf(c1[nt][1] + by, 0.f);
            float v2 = fmaxf(c1[nt][2] + bx, 0.f), v3 = fmaxf(c1[nt][3] + by, 0.f);
            if (row0 < N)
                *reinterpret_cast<float2*>(Y1 + (size_t)row0 * 64 + col) =
                    make_float2(v0, v1);
            if (row0 + 8 < N)
                *reinterpret_cast<float2*>(Y1 + (size_t)(row0 + 8) * 64 + col) =
                    make_float2(v2, v3);
        }
        {
            float bx = Bs2[col], by = Bs2[col + 1];
            float v0 = fmaxf(c2[nt][0] + bx, 0.f), v1 = fmaxf(c2[nt][1] + by, 0.f);
            float v2 = fmaxf(c2[nt][2] + bx, 0.f), v3 = fmaxf(c2[nt][3] + by, 0.f);
            if (row0 < N)
                *reinterpret_cast<__half2*>(Y2 + (size_t)row0 * 64 + col) =
                    __floats2half2_rn(v0, v1);
            if (row0 + 8 < N)
                *reinterpret_cast<__half2*>(Y2 + (size_t)(row0 + 8) * 64 + col) =
                    __floats2half2_rn(v2, v3);
        }
    }
}

// ---------------- small GEMM for r (F=48, N=1000) ----------------
template <int F, bool RELU, typename OUT>
__global__ void __launch_bounds__(128) gemm_small(
    const float* __restrict__ X, int N,
    const float* __restrict__ W, const float* __restrict__ B,
    OUT* __restrict__ Y)
{
    __shared__ float Wt[F * 64];
    __shared__ float Bs[64];
    const int tid = threadIdx.x;
    for (int i = tid; i < F * 64; i += 128) {
        int j = i / F;
        int k = i - j * F;
        Wt[k * 64 + j] = W[i];
    }
    if (tid < 64) Bs[tid] = B[tid];
    __syncthreads();
    const int row = blockIdx.x * 128 + tid;
    if (row >= N) return;
    float4 acc[16];
    const float4* Bs4 = reinterpret_cast<const float4*>(Bs);
#pragma unroll
    for (int j = 0; j < 16; j++) acc[j] = Bs4[j];
    const float4* X4  = reinterpret_cast<const float4*>(X + (size_t)row * F);
    const float4* Wt4 = reinterpret_cast<const float4*>(Wt);
#pragma unroll 2
    for (int k4 = 0; k4 < F / 4; k4++) {
        const float4 xv = X4[k4];
#pragma unroll
        for (int kk = 0; kk < 4; kk++) {
            const float xs = (kk == 0) ? xv.x : (kk == 1) ? xv.y : (kk == 2) ? xv.z : xv.w;
            const float4* wrow = Wt4 + (size_t)(k4 * 4 + kk) * 16;
#pragma unroll
            for (int j = 0; j < 16; j++) {
                float4 w = wrow[j];
                acc[j].x += xs * w.x; acc[j].y += xs * w.y;
                acc[j].z += xs * w.z; acc[j].w += xs * w.w;
            }
        }
    }
#pragma unroll
    for (int j = 0; j < 16; j++) {
        float4 v = acc[j];
        if (RELU) {
            v.x = fmaxf(v.x, 0.f); v.y = fmaxf(v.y, 0.f);
            v.z = fmaxf(v.z, 0.f); v.w = fmaxf(v.w, 0.f);
        }
        if constexpr (sizeof(OUT) == 2) {
            __half2* p = reinterpret_cast<__half2*>((__half*)Y + (size_t)row * 64 + j * 4);
            p[0] = __floats2half2_rn(v.x, v.y);
            p[1] = __floats2half2_rn(v.z, v.w);
        } else {
            reinterpret_cast<float4*>((float*)Y + (size_t)row * 64)[j] = v;
        }
    }
}

// ---------------- CSR build ----------------
__global__ void zero_kernel(int* p, int n) {
    int i = blockIdx.x * blockDim.x + threadIdx.x;
    if (i < n) p[i] = 0;
}

__global__ void hist_kernel4(const int* __restrict__ dxx, const int* __restrict__ dcx,
                             const int* __restrict__ drx,
                             int Exx, int Ecx, int Erx, int* __restrict__ deg)
{
    int base = (blockIdx.x * blockDim.x + threadIdx.x) * 4;
    int Etot = Exx + Ecx + Erx;
    int d[4];
    int cnt = 0;
#pragma unroll
    for (int j = 0; j < 4; j++) {
        int i = base + j;
        if (i < Etot) {
            if (i < Exx) d[cnt] = dxx[i];
            else if (i < Exx + Ecx) d[cnt] = dcx[i - Exx];
            else d[cnt] = drx[i - Exx - Ecx];
            cnt++;
        }
    }
#pragma unroll
    for (int j = 0; j < 4; j++)
        if (j < cnt) atomicAdd(&deg[d[j]], 1);
}

__global__ void scan1_kernel(const int* __restrict__ deg, int* __restrict__ off,
                             int* __restrict__ bsum, int n)
{
    __shared__ int s[1024];
    int t = threadIdx.x;
    int i = blockIdx.x * 1024 + t;
    int v = (i < n) ? deg[i] : 0;
    s[t] = v;
    __syncthreads();
#pragma unroll
    for (int o = 1; o < 1024; o <<= 1) {
        int a = (t >= o) ? s[t - o] : 0;
        __syncthreads();
        s[t] += a;
        __syncthreads();
    }
    if (i < n) off[i] = s[t] - v;
    if (t == 1023) bsum[blockIdx.x] = s[1023];
}

__global__ void scan2_kernel(int* __restrict__ bsum, int nb, int* __restrict__ off,
                             int n, int Etot)
{
    __shared__ int s[128];
    int t = threadIdx.x;
    int v = (t < nb) ? bsum[t] : 0;
    s[t] = v;
    __syncthreads();
#pragma unroll
    for (int o = 1; o < 128; o <<= 1) {
        int a = (t >= o) ? s[t - o] : 0;
        __syncthreads();
        s[t] += a;
        __syncthreads();
    }
    if (t < nb) bsum[t] = s[t] - v;
    if (t == 0) off[n] = Etot;
}

__global__ void scan3_kernel(int* __restrict__ off, const int* __restrict__ bsum,
                             int* __restrict__ cur, int n)
{
    int i = blockIdx.x * 1024 + threadIdx.x;
    if (i < n) {
        int o = off[i] + bsum[blockIdx.x];
        off[i] = o;
        cur[i] = o;
    }
}

__global__ void fill_kernel4(const int* __restrict__ sxx, const int* __restrict__ dxx,
                             const int* __restrict__ scx, const int* __restrict__ dcx,
                             const int* __restrict__ srx, const int* __restrict__ drx,
                             int Exx, int Ecx, int Erx,
                             int* __restrict__ cur, unsigned int* __restrict__ eidx)
{
    int base = (blockIdx.x * blockDim.x + threadIdx.x) * 4;
    int Etot = Exx + Ecx + Erx;
    int d[4]; unsigned int rec[4];
    int cnt = 0;
#pragma unroll
    for (int j = 0; j < 4; j++) {
        int i = base + j;
        if (i < Etot) {
            int dd, ss; unsigned int rel;
            if (i < Exx)            { dd = dxx[i];             ss = sxx[i];             rel = 0u; }
            else if (i < Exx + Ecx) { dd = dcx[i - Exx];       ss = scx[i - Exx];       rel = 1u; }
            else                    { dd = drx[i - Exx - Ecx]; ss = srx[i - Exx - Ecx]; rel = 2u; }
            d[cnt] = dd;
            rec[cnt] = (rel << 28) | (unsigned int)ss;
            cnt++;
        }
    }
#pragma unroll
    for (int j = 0; j < 4; j++) {
        if (j < cnt) {
            int p = atomicAdd(&cur[d[j]], 1);
            eidx[p] = rec[j];
        }
    }
}

// ---------------------------------------------------------------------------
// gather-accumulate v4: 8 lanes/edge (uint4), 32-edge main loop (MLP=8/lane)
// ---------------------------------------------------------------------------
__device__ __forceinline__ void acc8h(float4& a0, float4& a1,
                                      const __half* __restrict__ txx,
                                      const __half* __restrict__ tcx,
                                      const __half* __restrict__ trx,
                                      unsigned int rr, int q)
{
    const __half* t = (rr >> 28) == 0 ? txx : ((rr >> 28) == 1 ? tcx : trx);
    uint4 h = *reinterpret_cast<const uint4*>(
        t + (size_t)(rr & 0x0FFFFFFFu) * 64 + q * 8);
    const __half2* hp = reinterpret_cast<const __half2*>(&h);
    float2 f0 = __half22float2(hp[0]);
    float2 f1 = __half22float2(hp[1]);
    float2 f2 = __half22float2(hp[2]);
    float2 f3 = __half22float2(hp[3]);
    a0.x += f0.x; a0.y += f0.y; a0.z += f1.x; a0.w += f1.y;
    a1.x += f2.x; a1.y += f2.y; a1.z += f3.x; a1.w += f3.y;
}

__global__ void __launch_bounds__(256) gather_accum_v4(
    const __half* __restrict__ txx, const __half* __restrict__ tcx,
    const __half* __restrict__ trx,
    float* __restrict__ agg,
    const int* __restrict__ off, const unsigned int* __restrict__ eidx,
    int nx)
{
    const int warp = (blockIdx.x * 256 + threadIdx.x) >> 5;
    const int lane = threadIdx.x & 31;
    if (warp >= nx) return;
    const int quarter = lane >> 3;
    const int q       = lane & 7;
    const int s = off[warp];
    const int e = off[warp + 1];

    float4 a0 = make_float4(0.f, 0.f, 0.f, 0.f);
    float4 a1 = make_float4(0.f, 0.f, 0.f, 0.f);

    int i = s;
    for (; i + 32 <= e; i += 32) {
        unsigned int r0 = eidx[i      + quarter];
        unsigned int r1 = eidx[i + 4  + quarter];
        unsigned int r2 = eidx[i + 8  + quarter];
        unsigned int r3 = eidx[i + 12 + quarter];
        unsigned int r4 = eidx[i + 16 + quarter];
        unsigned int r5 = eidx[i + 20 + quarter];
        unsigned int r6 = eidx[i + 24 + quarter];
        unsigned int r7 = eidx[i + 28 + quarter];
        acc8h(a0, a1, txx, tcx, trx, r0, q);
        acc8h(a0, a1, txx, tcx, trx, r1, q);
        acc8h(a0, a1, txx, tcx, trx, r2, q);
        acc8h(a0, a1, txx, tcx, trx, r3, q);
        acc8h(a0, a1, txx, tcx, trx, r4, q);
        acc8h(a0, a1, txx, tcx, trx, r5, q);
        acc8h(a0, a1, txx, tcx, trx, r6, q);
        acc8h(a0, a1, txx, tcx, trx, r7, q);
    }
    for (; i + 16 <= e; i += 16) {
        unsigned int r0 = eidx[i      + quarter];
        unsigned int r1 = eidx[i + 4  + quarter];
        unsigned int r2 = eidx[i + 8  + quarter];
        unsigned int r3 = eidx[i + 12 + quarter];
        acc8h(a0, a1, txx, tcx, trx, r0, q);
        acc8h(a0, a1, txx, tcx, trx, r1, q);
        acc8h(a0, a1, txx, tcx, trx, r2, q);
        acc8h(a0, a1, txx, tcx, trx, r3, q);
    }
    for (; i + 4 <= e; i += 4) {
        acc8h(a0, a1, txx, tcx, trx, eidx[i + quarter], q);
    }
    if (quarter < e - i) {
        acc8h(a0, a1, txx, tcx, trx, eidx[i + quarter], q);
    }

#pragma unroll
    for (int m = 8; m <= 16; m <<= 1) {
        a0.x += __shfl_xor_sync(0xFFFFFFFFu, a0.x, m);
        a0.y += __shfl_xor_sync(0xFFFFFFFFu, a0.y, m);
        a0.z += __shfl_xor_sync(0xFFFFFFFFu, a0.z, m);
        a0.w += __shfl_xor_sync(0xFFFFFFFFu, a0.w, m);
        a1.x += __shfl_xor_sync(0xFFFFFFFFu, a1.x, m);
        a1.y += __shfl_xor_sync(0xFFFFFFFFu, a1.y, m);
        a1.z += __shfl_xor_sync(0xFFFFFFFFu, a1.z, m);
        a1.w += __shfl_xor_sync(0xFFFFFFFFu, a1.w, m);
    }

    if (quarter == 0) {
        float4* p = reinterpret_cast<float4*>(agg + (size_t)warp * 64 + q * 8);
        float4 b0 = p[0], b1 = p[1];
        b0.x += a0.x; b0.y += a0.y; b0.z += a0.z; b0.w += a0.w;
        b1.x += a1.x; b1.y += a1.y; b1.z += a1.z; b1.w += a1.w;
        p[0] = b0;
        p[1] = b1;
    }
}

extern "C" void kernel_launch(void* const* d_in, const int* in_sizes, int n_in,
                              void* d_out, int out_size)
{
    const float* x      = (const float*)d_in[0];
    const float* c      = (const float*)d_in[1];
    const float* r      = (const float*)d_in[2];
    const int*   e_xx_s = (const int*)d_in[3];
    const int*   e_xx_d = (const int*)d_in[4];
    const int*   e_cx_s = (const int*)d_in[5];
    const int*   e_cx_d = (const int*)d_in[6];
    const int*   e_rx_s = (const int*)d_in[7];
    const int*   e_rx_d = (const int*)d_in[8];
    const float* W_x    = (const float*)d_in[9];
    const float* b_x    = (const float*)d_in[10];
    const float* W_c    = (const float*)d_in[11];
    const float* b_c    = (const float*)d_in[12];
    const float* W_r    = (const float*)d_in[13];
    const float* b_r    = (const float*)d_in[14];
    const float* W_xx   = (const float*)d_in[15];
    const float* b_xx   = (const float*)d_in[16];
    const float* W_cx   = (const float*)d_in[17];
    const float* b_cx   = (const float*)d_in[18];
    const float* W_rx   = (const float*)d_in[19];
    const float* b_rx   = (const float*)d_in[20];
    const float* W_pool = (const float*)d_in[21];
    const float* b_pool = (const float*)d_in[22];

    const int nx  = in_sizes[0] / 64;
    const int nc  = in_sizes[1] / 32;
    const int nr  = in_sizes[2] / 48;
    const int Exx = in_sizes[3];
    const int Ecx = in_sizes[5];
    const int Erx = in_sizes[7];
    const int Etot = Exx + Ecx + Erx;

    float *agg, *txxf, *tcxf, *trxf;
    int *off, *cur, *bsum;
    unsigned int* eidx;
    cudaGetSymbolAddress((void**)&agg,  g_agg);
    cudaGetSymbolAddress((void**)&txxf, g_txx);
    cudaGetSymbolAddress((void**)&tcxf, g_tcx);
    cudaGetSymbolAddress((void**)&trxf, g_trx);
    cudaGetSymbolAddress((void**)&off,  g_off);
    cudaGetSymbolAddress((void**)&cur,  g_cur);
    cudaGetSymbolAddress((void**)&bsum, g_bsum);
    cudaGetSymbolAddress((void**)&eidx, g_eidx);
    __half* txx = (__half*)txxf;
    __half* tcx = (__half*)tcxf;
    __half* trx = (__half*)trxf;

    float* out   = (float*)d_out;
    float* x_out = out;
    float* c_out = out + (size_t)nx * 64;
    float* r_out = out + (size_t)nx * 64 + (size_t)nc * 64;

    const int gx = (nx + 127) / 128;
    const int gc = (nc + 127) / 128;
    const int gr = (nr + 127) / 128;
    const int nb = (nx + 1023) / 1024;

    // one-time (first, uncaptured correctness call) side-stream + events
    static cudaStream_t s_side = nullptr;
    static cudaEvent_t  ev_fork = nullptr, ev_join = nullptr;
    if (s_side == nullptr) {
        cudaStreamCreateWithFlags(&s_side, cudaStreamNonBlocking);
        cudaEventCreateWithFlags(&ev_fork, cudaEventDisableTiming);
        cudaEventCreateWithFlags(&ev_join, cudaEventDisableTiming);
        cudaFuncSetAttribute((const void*)hmma_gemm_dual<64>,
                             cudaFuncAttributeMaxDynamicSharedMemorySize, SMEM_DU);
        cudaFuncSetAttribute((const void*)hmma_gemm_dual<32>,
                             cudaFuncAttributeMaxDynamicSharedMemorySize, SMEM_DU);
        cudaFuncSetAttribute((const void*)hmma_gemm<64, false, float>,
                             cudaFuncAttributeMaxDynamicSharedMemorySize, SMEM_HM);
    }

    // ---- fork: CSR build + dual32 on side stream; dual64 + misc on main ----
    cudaEventRecord(ev_fork, 0);
    cudaStreamWaitEvent(s_side, ev_fork, 0);

    // side: CSR chain then the c-GEMM pair (balances ~52us vs main ~40us)
    hist_kernel4<<<(Etot / 4 + 256) / 256, 256, 0, s_side>>>(
        e_xx_d, e_cx_d, e_rx_d, Exx, Ecx, Erx, cur);
    scan1_kernel<<<nb, 1024, 0, s_side>>>(cur, off, bsum, nx);
    scan2_kernel<<<1, 128, 0, s_side>>>(bsum, nb, off, nx, Etot);
    scan3_kernel<<<nb, 1024, 0, s_side>>>(off, bsum, cur, nx);
    fill_kernel4<<<(Etot / 4 + 256) / 256, 256, 0, s_side>>>(
        e_xx_s, e_xx_d, e_cx_s, e_cx_d, e_rx_s, e_rx_d,
        Exx, Ecx, Erx, cur, eidx);
    hmma_gemm_dual<32><<<gc, 256, SMEM_DU, s_side>>>(c, nc, W_c, b_c, c_out,
                                                     W_cx, b_cx, tcx);
    cudaEventRecord(ev_join, s_side);

    // main: x-GEMM pair, r GEMMs, cur re-zero (all overlap the side chain)
    hmma_gemm_dual<64><<<gx, 256, SMEM_DU>>>(x, nx, W_x, b_x, agg,
                                             W_xx, b_xx, txx);
    gemm_small<48, true, __half><<<gr, 128>>>(r, nr, W_rx, b_rx, trx);
    gemm_small<48, true, float ><<<gr, 128>>>(r, nr, W_r,  b_r,  r_out);
    zero_kernel<<<(nx + 255) / 256, 256>>>(cur, nx);

    // ---- join: gather needs CSR + all tables ----
    cudaStreamWaitEvent(0, ev_join, 0);
    gather_accum_v4<<<(nx + 7) / 8, 256>>>(txx, tcx, trx, agg, off, eidx, nx);

    // ---- output projection ----
    hmma_gemm<64, false, float><<<gx, 256, SMEM_HM>>>(agg, nx, W_pool, b_pool, x_out);
}